// round 13
// baseline (speedup 1.0000x reference)
#include <cuda_runtime.h>

#define W 512
#define H 512
#define B 16
#define HW (H*W)

#define TX 64
#define TY 32

// Scratch: grayscale image (device global, no allocation)
__device__ float g_gray[B * HW];

// ---------------------------------------------------------------------------
// Kernel 1: gray + channel shuffle. Each thread: 2 float4 chunks.
// ---------------------------------------------------------------------------
__global__ __launch_bounds__(256) void k1_gray_shuffle(
    const float* __restrict__ x, const int* __restrict__ perm,
    float* __restrict__ x5)
{
    const int nv = HW / 4;
    const int half = nv / 2;
    int t = blockIdx.x * 256 + threadIdx.x;
    if (t >= B * half) return;
    int b = t / half;
    int p = t - b * half;

    const float4* xb = (const float4*)(x + (size_t)b * 3 * HW);
    float4 c0a = xb[p],          c0b = xb[p + half];
    float4 c1a = xb[nv + p],     c1b = xb[nv + p + half];
    float4 c2a = xb[2*nv + p],   c2b = xb[2*nv + p + half];

    float4 ga, gb;
    ga.x = 0.114f*c0a.x + 0.587f*c1a.x + 0.299f*c2a.x;
    ga.y = 0.114f*c0a.y + 0.587f*c1a.y + 0.299f*c2a.y;
    ga.z = 0.114f*c0a.z + 0.587f*c1a.z + 0.299f*c2a.z;
    ga.w = 0.114f*c0a.w + 0.587f*c1a.w + 0.299f*c2a.w;
    gb.x = 0.114f*c0b.x + 0.587f*c1b.x + 0.299f*c2b.x;
    gb.y = 0.114f*c0b.y + 0.587f*c1b.y + 0.299f*c2b.y;
    gb.z = 0.114f*c0b.z + 0.587f*c1b.z + 0.299f*c2b.z;
    gb.w = 0.114f*c0b.w + 0.587f*c1b.w + 0.299f*c2b.w;
    ((float4*)g_gray)[b * nv + p]        = ga;
    ((float4*)g_gray)[b * nv + p + half] = gb;

    int p0 = perm[b * 3 + 0];
    int p1 = perm[b * 3 + 1];
    int p2 = perm[b * 3 + 2];
    float4* o = (float4*)(x5 + (size_t)b * 3 * HW);
    o[p]               = (p0 == 0) ? c0a : ((p0 == 1) ? c1a : c2a);
    o[p + half]        = (p0 == 0) ? c0b : ((p0 == 1) ? c1b : c2b);
    o[nv + p]          = (p1 == 0) ? c0a : ((p1 == 1) ? c1a : c2a);
    o[nv + p + half]   = (p1 == 0) ? c0b : ((p1 == 1) ? c1b : c2b);
    o[2*nv + p]        = (p2 == 0) ? c0a : ((p2 == 1) ? c1a : c2a);
    o[2*nv + p + half] = (p2 == 0) ? c0b : ((p2 == 1) ? c1b : c2b);
}

// ---------------------------------------------------------------------------
// Fused kernel: blur(reflect) -> sobel(replicate) -> mag -> NMS(zero) ->
// 4 dilations, all in smem. 64x32 tile, 512 threads.
// Interior blocks: fully vectorized float4 path (no clamps).
// Border blocks: scalar path with clamps (identical arithmetic).
//
// Buffers (strides chosen for 16B alignment), overlapping pool (48384 B):
//   sg   48x88 f  @15360  (gray,  rows ty0-8..+39, cols tx0-12..+75)  A..B
//   st   48x80 f  @0      (h-blur, cols tx0-8..+71)                   B..C
//   sb   44x80 f  @15360  (blur,  rows ty0-6..+37)                    C..D
//   smag 42x76 f  @29440  (mag,   rows ty0-5..+36, cols tx0-6..+69)   D..E
//   sax  40x72 u8 @42208                                              D..E
//   ss   40x72 f  @0      (nms,   rows ty0-4..+35, cols tx0-4..+67)   E..G
//   v3/5/7/9 32x72 f @11520/20736/29952/39168                         F..G
// ---------------------------------------------------------------------------
__device__ __forceinline__ int refl(int i, int n) {
    if (i < 0) i = -i;
    if (i >= n) i = 2 * n - 2 - i;
    return i;
}

__global__ __launch_bounds__(512) void kF_canny_dilate(
    float* __restrict__ outmag,
    float* __restrict__ o3, float* __restrict__ o5,
    float* __restrict__ o7, float* __restrict__ o9)
{
    __shared__ __align__(16) char pool[48384];
    float* ss          = (float*)(pool + 0);
    float* st          = (float*)(pool + 0);
    float* v3          = (float*)(pool + 11520);
    float* v5          = (float*)(pool + 20736);
    float* v7          = (float*)(pool + 29952);
    float* v9          = (float*)(pool + 39168);
    float* sg          = (float*)(pool + 15360);
    float* sb          = (float*)(pool + 15360);
    float* smag        = (float*)(pool + 29440);
    unsigned char* sax = (unsigned char*)(pool + 42208);

    const int tid = threadIdx.x;
    const int b = blockIdx.z;
    const int ty0 = blockIdx.y * TY;
    const int tx0 = blockIdx.x * TX;
    const float* g = g_gray + (size_t)b * HW;
    const bool border = (blockIdx.x == 0) | (blockIdx.x == (W/TX - 1)) |
                        (blockIdx.y == 0) | (blockIdx.y == (H/TY - 1));

    const float w0 = 0.05448868f, w1 = 0.24420136f, w2 = 0.40261996f;

    // ---- Stage A: gray load. sg 48x88, origin (ty0-8, tx0-12)
    if (!border) {
        for (int i = tid; i < 48 * 22; i += 512) {
            int r = i / 22, c4 = i - 22 * r;
            *(float4*)&sg[r * 88 + c4 * 4] =
                *(const float4*)(g + (ty0 + r - 8) * W + tx0 - 12 + c4 * 4);
        }
    } else {
        for (int i = tid; i < 48 * 88; i += 512) {
            int r = i / 88, c = i - 88 * r;
            sg[r * 88 + c] = g[refl(ty0 + r - 8, H) * W + refl(tx0 + c - 12, W)];
        }
    }
    __syncthreads();

    // ---- Stage B: horizontal blur. st 48x80, origin col tx0-8
    // st[r][c] = w0*(sg[c+2]+sg[c+6]) + w1*(sg[c+3]+sg[c+5]) + w2*sg[c+4]
    if (!border) {
        for (int i = tid; i < 48 * 20; i += 512) {
            int r = i / 20, j = (i - 20 * r) * 4;
            const float* p = &sg[r * 88 + j];
            float4 a0 = *(const float4*)p;
            float4 a1 = *(const float4*)(p + 4);
            float4 a2 = *(const float4*)(p + 8);
            float4 o;
            o.x = w0*(a0.z + a1.z) + w1*(a0.w + a1.y) + w2*a1.x;
            o.y = w0*(a0.w + a1.w) + w1*(a1.x + a1.z) + w2*a1.y;
            o.z = w0*(a1.x + a2.x) + w1*(a1.y + a1.w) + w2*a1.z;
            o.w = w0*(a1.y + a2.y) + w1*(a1.z + a2.x) + w2*a1.w;
            *(float4*)&st[r * 80 + j] = o;
        }
    } else {
        for (int i = tid; i < 48 * 80; i += 512) {
            int r = i / 80, c = i - 80 * r;
            const float* p = &sg[r * 88 + c + 2];
            st[i] = w0*(p[0] + p[4]) + w1*(p[1] + p[3]) + w2*p[2];
        }
    }
    __syncthreads();

    // ---- Stage C: vertical blur. sb 44x80, origin row ty0-6
    if (!border) {
        for (int i = tid; i < 44 * 20; i += 512) {
            int r = i / 20, j = (i - 20 * r) * 4;
            const float* p = &st[r * 80 + j];
            float4 q0 = *(const float4*)p;
            float4 q1 = *(const float4*)(p + 80);
            float4 q2 = *(const float4*)(p + 160);
            float4 q3 = *(const float4*)(p + 240);
            float4 q4 = *(const float4*)(p + 320);
            float4 o;
            o.x = w0*(q0.x + q4.x) + w1*(q1.x + q3.x) + w2*q2.x;
            o.y = w0*(q0.y + q4.y) + w1*(q1.y + q3.y) + w2*q2.y;
            o.z = w0*(q0.z + q4.z) + w1*(q1.z + q3.z) + w2*q2.z;
            o.w = w0*(q0.w + q4.w) + w1*(q1.w + q3.w) + w2*q2.w;
            *(float4*)&sb[r * 80 + j] = o;
        }
    } else {
        for (int i = tid; i < 44 * 80; i += 512) {
            int r = i / 80, c = i - 80 * r;
            const float* p = &st[r * 80 + c];
            sb[i] = w0*(p[0] + p[4*80]) + w1*(p[80] + p[3*80]) + w2*p[2*80];
        }
    }
    __syncthreads();

    // ---- Stage D: sobel magnitude. smag 42x76, origin (ty0-5, tx0-6).
    // smag[r][j] uses sb rows r..r+2, cols j+1..j+3. axis for ss region.
    if (!border) {
        for (int i = tid; i < 42 * 19; i += 512) {
            int r = i / 19, j = (i - 19 * r) * 4;
            const float* p = &sb[r * 80 + j];
            float t0[8], t1[8], t2[8];
            *(float4*)&t0[0] = *(const float4*)p;
            *(float4*)&t0[4] = *(const float4*)(p + 4);
            *(float4*)&t1[0] = *(const float4*)(p + 80);
            *(float4*)&t1[4] = *(const float4*)(p + 84);
            *(float4*)&t2[0] = *(const float4*)(p + 160);
            *(float4*)&t2[4] = *(const float4*)(p + 164);
            float4 vv;
            float* pv = (float*)&vv;
            #pragma unroll
            for (int k = 0; k < 4; k++) {
                float b00 = t0[k+1], b01 = t0[k+2], b02 = t0[k+3];
                float b10 = t1[k+1],                b12 = t1[k+3];
                float b20 = t2[k+1], b21 = t2[k+2], b22 = t2[k+3];
                float gxv = (b02 - b00) + 2.f * (b12 - b10) + (b22 - b20);
                float gyv = (b20 - b00) + 2.f * (b21 - b01) + (b22 - b02);
                pv[k] = sqrtf(gxv * gxv + gyv * gyv + 1e-6f);
                int sc = j + k - 2;
                if ((unsigned)(r - 1) < 40u && (unsigned)sc < 72u) {
                    float ax = fabsf(gxv), ay = fabsf(gyv);
                    int axis;
                    if (ay < 0.41421356f * ax)      axis = 0;
                    else if (ay > 2.41421356f * ax) axis = 2;
                    else axis = (gxv * gyv >= 0.f) ? 1 : 3;
                    sax[(r - 1) * 72 + sc] = (unsigned char)axis;
                }
            }
            *(float4*)&smag[r * 76 + j] = vv;
        }
    } else {
        for (int i = tid; i < 42 * 76; i += 512) {
            int r = i / 76, c = i - 76 * r;
            int gy = ty0 + r - 5, gx = tx0 + c - 6;
            float v = 0.f;
            if (gy >= 0 && gy < H && gx >= 0 && gx < W) {
                int ym = max(gy - 1, 0) - ty0 + 6;
                int yc = gy - ty0 + 6;
                int yp = min(gy + 1, H - 1) - ty0 + 6;
                int xm = max(gx - 1, 0) - tx0 + 8;
                int xc = gx - tx0 + 8;
                int xp = min(gx + 1, W - 1) - tx0 + 8;
                float b00 = sb[ym*80+xm], b01 = sb[ym*80+xc], b02 = sb[ym*80+xp];
                float b10 = sb[yc*80+xm],                      b12 = sb[yc*80+xp];
                float b20 = sb[yp*80+xm], b21 = sb[yp*80+xc], b22 = sb[yp*80+xp];
                float gxv = (b02 - b00) + 2.f * (b12 - b10) + (b22 - b20);
                float gyv = (b20 - b00) + 2.f * (b21 - b01) + (b22 - b02);
                v = sqrtf(gxv * gxv + gyv * gyv + 1e-6f);
                if ((unsigned)(r - 1) < 40u && (unsigned)(c - 2) < 72u) {
                    float ax = fabsf(gxv), ay = fabsf(gyv);
                    int axis;
                    if (ay < 0.41421356f * ax)      axis = 0;
                    else if (ay > 2.41421356f * ax) axis = 2;
                    else axis = (gxv * gyv >= 0.f) ? 1 : 3;
                    sax[(r - 1) * 72 + (c - 2)] = (unsigned char)axis;
                }
            }
            smag[i] = v;
        }
    }
    __syncthreads();

    // ---- Stage E: NMS. ss 40x72, origin (ty0-4, tx0-4). smag idx = (+1, +2)
    for (int i = tid; i < 40 * 72; i += 512) {
        int rs = i / 72, cs = i - 72 * rs;
        float res = 0.f;
        bool ok = true;
        if (border) {
            int gy = ty0 + rs - 4, gx = tx0 + cs - 4;
            ok = (gy >= 0 && gy < H && gx >= 0 && gx < W);
        }
        if (ok) {
            int axis = sax[i];
            int dy = (axis == 0) ? 0 : 1;
            int dx = (axis == 2) ? 0 : ((axis == 3) ? -1 : 1);
            float m   = smag[(rs + 1) * 76 + cs + 2];
            float pos = m - smag[(rs + 1 + dy) * 76 + cs + 2 + dx];
            float neg = m - smag[(rs + 1 - dy) * 76 + cs + 2 - dx];
            res = (fminf(pos, neg) > 0.f) ? m : 0.f;
        }
        ss[i] = res;
    }
    __syncthreads();

    // ---- Stage F: vertical incremental maxes (float4), rows 0..31 x 72 cols
    for (int i = tid; i < 32 * 18; i += 512) {
        int r = i / 18, j = (i - 18 * r) * 4;
        const float* p = &ss[r * 72 + j];
        float4 s0 = *(const float4*)p;
        float4 s1 = *(const float4*)(p + 72);
        float4 s2 = *(const float4*)(p + 144);
        float4 s3 = *(const float4*)(p + 216);
        float4 s4 = *(const float4*)(p + 288);
        float4 s5 = *(const float4*)(p + 360);
        float4 s6 = *(const float4*)(p + 432);
        float4 s7 = *(const float4*)(p + 504);
        float4 s8 = *(const float4*)(p + 576);
        float4 m3, m5, m7, m9;
        m3.x = fmaxf(fmaxf(s3.x, s4.x), s5.x);
        m3.y = fmaxf(fmaxf(s3.y, s4.y), s5.y);
        m3.z = fmaxf(fmaxf(s3.z, s4.z), s5.z);
        m3.w = fmaxf(fmaxf(s3.w, s4.w), s5.w);
        m5.x = fmaxf(m3.x, fmaxf(s2.x, s6.x));
        m5.y = fmaxf(m3.y, fmaxf(s2.y, s6.y));
        m5.z = fmaxf(m3.z, fmaxf(s2.z, s6.z));
        m5.w = fmaxf(m3.w, fmaxf(s2.w, s6.w));
        m7.x = fmaxf(m5.x, fmaxf(s1.x, s7.x));
        m7.y = fmaxf(m5.y, fmaxf(s1.y, s7.y));
        m7.z = fmaxf(m5.z, fmaxf(s1.z, s7.z));
        m7.w = fmaxf(m5.w, fmaxf(s1.w, s7.w));
        m9.x = fmaxf(m7.x, fmaxf(s0.x, s8.x));
        m9.y = fmaxf(m7.y, fmaxf(s0.y, s8.y));
        m9.z = fmaxf(m7.z, fmaxf(s0.z, s8.z));
        m9.w = fmaxf(m7.w, fmaxf(s0.w, s8.w));
        int o = r * 72 + j;
        *(float4*)&v3[o] = m3;
        *(float4*)&v5[o] = m5;
        *(float4*)&v7[o] = m7;
        *(float4*)&v9[o] = m9;
    }
    __syncthreads();

    // ---- Stage G: horizontal maxes + all stores (mag + 4 dilations)
    {
        int i = tid;
        int y = i / 16, x4 = (i - 16 * y) * 4;

        float4 mg = *(const float4*)&ss[(y + 4) * 72 + (x4 + 4)];

        float4 r3, r5, r7, r9;
        float *p3 = (float*)&r3, *p5 = (float*)&r5, *p7 = (float*)&r7, *p9 = (float*)&r9;
        #pragma unroll
        for (int j = 0; j < 4; j++) {
            int base = y * 72 + x4 + j;
            float a3 = fmaxf(fmaxf(v3[base + 3], v3[base + 4]), v3[base + 5]);
            float a5 = fmaxf(fmaxf(v5[base + 2], v5[base + 3]),
                       fmaxf(v5[base + 4], fmaxf(v5[base + 5], v5[base + 6])));
            float a7 = fmaxf(fmaxf(fmaxf(v7[base + 1], v7[base + 2]),
                                   fmaxf(v7[base + 3], v7[base + 4])),
                             fmaxf(fmaxf(v7[base + 5], v7[base + 6]), v7[base + 7]));
            float a9 = fmaxf(fmaxf(fmaxf(fmaxf(v9[base + 0], v9[base + 1]),
                                         fmaxf(v9[base + 2], v9[base + 3])),
                                   fmaxf(fmaxf(v9[base + 4], v9[base + 5]),
                                         fmaxf(v9[base + 6], v9[base + 7]))),
                             v9[base + 8]);
            p3[j] = a3; p5[j] = a5; p7[j] = a7; p9[j] = a9;
        }
        size_t o = (size_t)b * HW + (size_t)(ty0 + y) * W + tx0 + x4;
        *(float4*)&outmag[o] = mg;
        *(float4*)&o3[o] = r3;
        *(float4*)&o5[o] = r5;
        *(float4*)&o7[o] = r7;
        *(float4*)&o9[o] = r9;
    }
}

// ---------------------------------------------------------------------------
extern "C" void kernel_launch(void* const* d_in, const int* in_sizes, int n_in,
                              void* d_out, int out_size)
{
    const float* x    = (const float*)d_in[0];
    const int*   perm = (const int*)d_in[1];
    float* out = (float*)d_out;

    float* o_mag = out;
    float* o_d3  = out + 1 * (size_t)B * HW;
    float* o_d5  = out + 2 * (size_t)B * HW;
    float* o_d7  = out + 3 * (size_t)B * HW;
    float* o_d9  = out + 4 * (size_t)B * HW;
    float* o_x5  = out + 5 * (size_t)B * HW;

    int nthreads1 = B * (HW / 8);
    k1_gray_shuffle<<<(nthreads1 + 255) / 256, 256>>>(x, perm, o_x5);

    dim3 g2(W / TX, H / TY, B);
    kF_canny_dilate<<<g2, 512>>>(o_mag, o_d3, o_d5, o_d7, o_d9);
}

// round 15
// speedup vs baseline: 1.1754x; 1.1754x over previous
#include <cuda_runtime.h>

#define W 512
#define H 512
#define B 16
#define HW (H*W)

#define TX 64
#define TY 32

// Scratch: grayscale image (device global, no allocation)
__device__ float g_gray[B * HW];

// ---------------------------------------------------------------------------
// Kernel 1: gray + channel shuffle. Each thread: 2 float4 chunks.
// ---------------------------------------------------------------------------
__global__ __launch_bounds__(256) void k1_gray_shuffle(
    const float* __restrict__ x, const int* __restrict__ perm,
    float* __restrict__ x5)
{
    const int nv = HW / 4;
    const int half = nv / 2;
    int t = blockIdx.x * 256 + threadIdx.x;
    if (t >= B * half) return;
    int b = t / half;
    int p = t - b * half;

    const float4* xb = (const float4*)(x + (size_t)b * 3 * HW);
    float4 c0a = xb[p],          c0b = xb[p + half];
    float4 c1a = xb[nv + p],     c1b = xb[nv + p + half];
    float4 c2a = xb[2*nv + p],   c2b = xb[2*nv + p + half];

    float4 ga, gb;
    ga.x = 0.114f*c0a.x + 0.587f*c1a.x + 0.299f*c2a.x;
    ga.y = 0.114f*c0a.y + 0.587f*c1a.y + 0.299f*c2a.y;
    ga.z = 0.114f*c0a.z + 0.587f*c1a.z + 0.299f*c2a.z;
    ga.w = 0.114f*c0a.w + 0.587f*c1a.w + 0.299f*c2a.w;
    gb.x = 0.114f*c0b.x + 0.587f*c1b.x + 0.299f*c2b.x;
    gb.y = 0.114f*c0b.y + 0.587f*c1b.y + 0.299f*c2b.y;
    gb.z = 0.114f*c0b.z + 0.587f*c1b.z + 0.299f*c2b.z;
    gb.w = 0.114f*c0b.w + 0.587f*c1b.w + 0.299f*c2b.w;
    ((float4*)g_gray)[b * nv + p]        = ga;
    ((float4*)g_gray)[b * nv + p + half] = gb;

    int p0 = perm[b * 3 + 0];
    int p1 = perm[b * 3 + 1];
    int p2 = perm[b * 3 + 2];
    float4* o = (float4*)(x5 + (size_t)b * 3 * HW);
    o[p]               = (p0 == 0) ? c0a : ((p0 == 1) ? c1a : c2a);
    o[p + half]        = (p0 == 0) ? c0b : ((p0 == 1) ? c1b : c2b);
    o[nv + p]          = (p1 == 0) ? c0a : ((p1 == 1) ? c1a : c2a);
    o[nv + p + half]   = (p1 == 0) ? c0b : ((p1 == 1) ? c1b : c2b);
    o[2*nv + p]        = (p2 == 0) ? c0a : ((p2 == 1) ? c1a : c2a);
    o[2*nv + p + half] = (p2 == 0) ? c0b : ((p2 == 1) ? c1b : c2b);
}

// ---------------------------------------------------------------------------
// Kernel 2: fused gaussian(reflect) -> sobel(replicate) -> magnitude ->
// NMS(zero pad). 64x32 tile, 512 threads. Blur stages float4-vectorized
// (named vars only); Sobel stage interior/border split.
// ---------------------------------------------------------------------------
__device__ __forceinline__ int refl(int i, int n) {
    if (i < 0) i = -i;
    if (i >= n) i = 2 * n - 2 - i;
    return i;
}

__global__ __launch_bounds__(512) void k2_canny(float* __restrict__ outmag)
{
    __shared__ float sg[40 * 72];            // gray: rows -4..35, cols -4..67
    __shared__ float st[40 * 68];            // h-blur: rows -4..35, cols -2..65
    __shared__ float sb[36 * 68];            // blur: rows -2..33, cols -2..65
    __shared__ float sm[34 * 66];            // mag: rows -1..32, cols -1..64
    __shared__ unsigned char sax[32 * 64];   // NMS axis per output pixel

    const int tid = threadIdx.x;
    const int b = blockIdx.z;
    const int ty0 = blockIdx.y * TY;
    const int tx0 = blockIdx.x * TX;
    const float* g = g_gray + (size_t)b * HW;
    const bool xborder = (blockIdx.x == 0) | (blockIdx.x == (W/TX - 1));
    const bool border  = xborder | (blockIdx.y == 0) | (blockIdx.y == (H/TY - 1));

    // ---- Stage A: gray load (rows refl, cols refl for border only)
    if (!xborder) {
        for (int i = tid; i < 40 * 18; i += 512) {
            int r = i / 18, c4 = i - 18 * r;
            int gyr = refl(ty0 + r - 4, H);
            const float4* row = (const float4*)(g + gyr * W + tx0 - 4);
            *(float4*)&sg[r * 72 + c4 * 4] = row[c4];
        }
    } else {
        for (int i = tid; i < 40 * 72; i += 512) {
            int r = i / 72, c = i - 72 * r;
            sg[i] = g[refl(ty0 + r - 4, H) * W + refl(tx0 + c - 4, W)];
        }
    }
    __syncthreads();

    // Gaussian 5-tap (sigma=1)
    const float w0 = 0.05448868f, w1 = 0.24420136f, w2 = 0.40261996f;

    // ---- Stage B: horizontal blur (float4). st[r][c] = taps sg[r][c..c+4]
    for (int i = tid; i < 40 * 17; i += 512) {
        int r = i / 17, j = (i - 17 * r) * 4;
        const float* p = &sg[r * 72 + j];
        float4 a0 = *(const float4*)p;
        float4 a1 = *(const float4*)(p + 4);
        float4 o;
        o.x = w0*(a0.x + a1.x) + w1*(a0.y + a0.w) + w2*a0.z;
        o.y = w0*(a0.y + a1.y) + w1*(a0.z + a1.x) + w2*a0.w;
        o.z = w0*(a0.z + a1.z) + w1*(a0.w + a1.y) + w2*a1.x;
        o.w = w0*(a0.w + a1.w) + w1*(a1.x + a1.z) + w2*a1.y;
        *(float4*)&st[r * 68 + j] = o;
    }
    __syncthreads();

    // ---- Stage C: vertical blur (float4). sb[r][c] = taps st[r..r+4][c]
    for (int i = tid; i < 36 * 17; i += 512) {
        int r = i / 17, j = (i - 17 * r) * 4;
        const float* p = &st[r * 68 + j];
        float4 q0 = *(const float4*)p;
        float4 q1 = *(const float4*)(p + 68);
        float4 q2 = *(const float4*)(p + 136);
        float4 q3 = *(const float4*)(p + 204);
        float4 q4 = *(const float4*)(p + 272);
        float4 o;
        o.x = w0*(q0.x + q4.x) + w1*(q1.x + q3.x) + w2*q2.x;
        o.y = w0*(q0.y + q4.y) + w1*(q1.y + q3.y) + w2*q2.y;
        o.z = w0*(q0.z + q4.z) + w1*(q1.z + q3.z) + w2*q2.z;
        o.w = w0*(q0.w + q4.w) + w1*(q1.w + q3.w) + w2*q2.w;
        *(float4*)&sb[r * 68 + j] = o;
    }
    __syncthreads();

    // ---- Stage D: magnitude rows -1..32, cols -1..64 (+ NMS axis)
    if (!border) {
        for (int i = tid; i < 34 * 66; i += 512) {
            int r = i / 66, c = i - 66 * r;
            // interior: ym=r, yc=r+1, yp=r+2; xm=c, xc=c+1, xp=c+2
            const float* p = &sb[r * 68 + c];
            float b00 = p[0],   b01 = p[1],   b02 = p[2];
            float b10 = p[68],                 b12 = p[70];
            float b20 = p[136], b21 = p[137], b22 = p[138];
            float gxv = (b02 - b00) + 2.f * (b12 - b10) + (b22 - b20);
            float gyv = (b20 - b00) + 2.f * (b21 - b01) + (b22 - b02);
            float v = sqrtf(gxv * gxv + gyv * gyv + 1e-6f);
            if ((unsigned)(r - 1) < 32u && (unsigned)(c - 1) < 64u) {
                float ax = fabsf(gxv), ay = fabsf(gyv);
                int axis;
                if (ay < 0.41421356f * ax)      axis = 0;   // tan(22.5)
                else if (ay > 2.41421356f * ax) axis = 2;   // tan(67.5)
                else axis = (gxv * gyv >= 0.f) ? 1 : 3;
                sax[(r - 1) * 64 + (c - 1)] = (unsigned char)axis;
            }
            sm[i] = v;
        }
    } else {
        for (int i = tid; i < 34 * 66; i += 512) {
            int r = i / 66, c = i - 66 * r;
            int gy = ty0 + r - 1, gx = tx0 + c - 1;
            float v = 0.f;
            if (gy >= 0 && gy < H && gx >= 0 && gx < W) {
                int ym = max(gy - 1, 0) - ty0 + 2;
                int yc = gy - ty0 + 2;
                int yp = min(gy + 1, H - 1) - ty0 + 2;
                int xm = max(gx - 1, 0) - tx0 + 2;
                int xc = gx - tx0 + 2;
                int xp = min(gx + 1, W - 1) - tx0 + 2;
                float b00 = sb[ym * 68 + xm], b01 = sb[ym * 68 + xc], b02 = sb[ym * 68 + xp];
                float b10 = sb[yc * 68 + xm],                          b12 = sb[yc * 68 + xp];
                float b20 = sb[yp * 68 + xm], b21 = sb[yp * 68 + xc], b22 = sb[yp * 68 + xp];
                float gxv = (b02 - b00) + 2.f * (b12 - b10) + (b22 - b20);
                float gyv = (b20 - b00) + 2.f * (b21 - b01) + (b22 - b02);
                v = sqrtf(gxv * gxv + gyv * gyv + 1e-6f);
                if ((unsigned)(r - 1) < 32u && (unsigned)(c - 1) < 64u) {
                    float ax = fabsf(gxv), ay = fabsf(gyv);
                    int axis;
                    if (ay < 0.41421356f * ax)      axis = 0;
                    else if (ay > 2.41421356f * ax) axis = 2;
                    else axis = (gxv * gyv >= 0.f) ? 1 : 3;
                    sax[(r - 1) * 64 + (c - 1)] = (unsigned char)axis;
                }
            }
            sm[i] = v;
        }
    }
    __syncthreads();

    // ---- NMS + float4 store: each thread one float4 (4 adjacent x)
    {
        int i = tid;
        int y = i / 16, x4 = (i - 16 * y) * 4;
        float4 r4;
        float* rr = (float*)&r4;
        #pragma unroll
        for (int j = 0; j < 4; j++) {
            int x = x4 + j;
            int axis = sax[y * 64 + x];
            int dy = (axis == 0) ? 0 : 1;
            int dx = (axis == 2) ? 0 : ((axis == 3) ? -1 : 1);
            float m   = sm[(y + 1) * 66 + (x + 1)];
            float pos = m - sm[(y + 1 + dy) * 66 + (x + 1 + dx)];
            float neg = m - sm[(y + 1 - dy) * 66 + (x + 1 - dx)];
            rr[j] = (fminf(pos, neg) > 0.f) ? m : 0.f;
        }
        *(float4*)&outmag[(size_t)b * HW + (size_t)(ty0 + y) * W + tx0 + x4] = r4;
    }
}

// ---------------------------------------------------------------------------
// Kernel 3: 4 dilations (SAME max-pool, k=3,5,7,9) in one pass.
// 64x32 tile, 512 threads. Vertical max stage float4-vectorized.
// ---------------------------------------------------------------------------
__global__ __launch_bounds__(512) void k3_dilate(
    const float* __restrict__ mag,
    float* __restrict__ o3, float* __restrict__ o5,
    float* __restrict__ o7, float* __restrict__ o9)
{
    __shared__ float s [40 * 72];         // mag: rows -4..35, cols -4..67 (0 outside)
    __shared__ float v3[32 * 72];
    __shared__ float v5[32 * 72];
    __shared__ float v7[32 * 72];
    __shared__ float v9[32 * 72];

    const int tid = threadIdx.x;
    const int b = blockIdx.z;
    const int ty0 = blockIdx.y * TY;
    const int tx0 = blockIdx.x * TX;
    const float* m = mag + (size_t)b * HW;
    const bool xborder = (blockIdx.x == 0) | (blockIdx.x == (W/TX - 1));

    if (!xborder) {
        for (int i = tid; i < 40 * 18; i += 512) {
            int r = i / 18, c4 = i - 18 * r;
            int gy = ty0 + r - 4;
            float4 v = make_float4(0.f, 0.f, 0.f, 0.f);
            if (gy >= 0 && gy < H)
                v = *(const float4*)(m + gy * W + tx0 - 4 + c4 * 4);
            *(float4*)&s[r * 72 + c4 * 4] = v;
        }
    } else {
        for (int i = tid; i < 40 * 72; i += 512) {
            int r = i / 72, c = i - 72 * r;
            int gy = ty0 + r - 4, gx = tx0 + c - 4;
            s[i] = (gy >= 0 && gy < H && gx >= 0 && gx < W) ? m[gy * W + gx] : 0.f;
        }
    }
    __syncthreads();

    // vertical incremental maxes (float4): output rows 0..31, all 72 cols
    for (int i = tid; i < 32 * 18; i += 512) {
        int r = i / 18, j = (i - 18 * r) * 4;
        const float* p = &s[r * 72 + j];
        float4 s0 = *(const float4*)p;
        float4 s1 = *(const float4*)(p + 72);
        float4 s2 = *(const float4*)(p + 144);
        float4 s3 = *(const float4*)(p + 216);
        float4 s4 = *(const float4*)(p + 288);
        float4 s5 = *(const float4*)(p + 360);
        float4 s6 = *(const float4*)(p + 432);
        float4 s7 = *(const float4*)(p + 504);
        float4 s8 = *(const float4*)(p + 576);
        float4 m3, m5, m7, m9;
        m3.x = fmaxf(fmaxf(s3.x, s4.x), s5.x);
        m3.y = fmaxf(fmaxf(s3.y, s4.y), s5.y);
        m3.z = fmaxf(fmaxf(s3.z, s4.z), s5.z);
        m3.w = fmaxf(fmaxf(s3.w, s4.w), s5.w);
        m5.x = fmaxf(m3.x, fmaxf(s2.x, s6.x));
        m5.y = fmaxf(m3.y, fmaxf(s2.y, s6.y));
        m5.z = fmaxf(m3.z, fmaxf(s2.z, s6.z));
        m5.w = fmaxf(m3.w, fmaxf(s2.w, s6.w));
        m7.x = fmaxf(m5.x, fmaxf(s1.x, s7.x));
        m7.y = fmaxf(m5.y, fmaxf(s1.y, s7.y));
        m7.z = fmaxf(m5.z, fmaxf(s1.z, s7.z));
        m7.w = fmaxf(m5.w, fmaxf(s1.w, s7.w));
        m9.x = fmaxf(m7.x, fmaxf(s0.x, s8.x));
        m9.y = fmaxf(m7.y, fmaxf(s0.y, s8.y));
        m9.z = fmaxf(m7.z, fmaxf(s0.z, s8.z));
        m9.w = fmaxf(m7.w, fmaxf(s0.w, s8.w));
        int o = r * 72 + j;
        *(float4*)&v3[o] = m3;
        *(float4*)&v5[o] = m5;
        *(float4*)&v7[o] = m7;
        *(float4*)&v9[o] = m9;
    }
    __syncthreads();

    // horizontal pass: each thread one float4 per output array
    {
        int i = tid;
        int y = i / 16, x4 = (i - 16 * y) * 4;
        float4 r3, r5, r7, r9;
        float *p3 = (float*)&r3, *p5 = (float*)&r5, *p7 = (float*)&r7, *p9 = (float*)&r9;
        #pragma unroll
        for (int j = 0; j < 4; j++) {
            int base = y * 72 + x4 + j;   // center col is x+4
            float a3 = fmaxf(fmaxf(v3[base + 3], v3[base + 4]), v3[base + 5]);
            float a5 = fmaxf(fmaxf(v5[base + 2], v5[base + 3]),
                       fmaxf(v5[base + 4], fmaxf(v5[base + 5], v5[base + 6])));
            float a7 = fmaxf(fmaxf(fmaxf(v7[base + 1], v7[base + 2]),
                                   fmaxf(v7[base + 3], v7[base + 4])),
                             fmaxf(fmaxf(v7[base + 5], v7[base + 6]), v7[base + 7]));
            float a9 = fmaxf(fmaxf(fmaxf(fmaxf(v9[base + 0], v9[base + 1]),
                                         fmaxf(v9[base + 2], v9[base + 3])),
                                   fmaxf(fmaxf(v9[base + 4], v9[base + 5]),
                                         fmaxf(v9[base + 6], v9[base + 7]))),
                             v9[base + 8]);
            p3[j] = a3; p5[j] = a5; p7[j] = a7; p9[j] = a9;
        }
        size_t o = (size_t)b * HW + (size_t)(ty0 + y) * W + tx0 + x4;
        *(float4*)&o3[o] = r3;
        *(float4*)&o5[o] = r5;
        *(float4*)&o7[o] = r7;
        *(float4*)&o9[o] = r9;
    }
}

// ---------------------------------------------------------------------------
extern "C" void kernel_launch(void* const* d_in, const int* in_sizes, int n_in,
                              void* d_out, int out_size)
{
    const float* x    = (const float*)d_in[0];
    const int*   perm = (const int*)d_in[1];
    float* out = (float*)d_out;

    float* o_mag = out;
    float* o_d3  = out + 1 * (size_t)B * HW;
    float* o_d5  = out + 2 * (size_t)B * HW;
    float* o_d7  = out + 3 * (size_t)B * HW;
    float* o_d9  = out + 4 * (size_t)B * HW;
    float* o_x5  = out + 5 * (size_t)B * HW;

    int nthreads1 = B * (HW / 8);
    k1_gray_shuffle<<<(nthreads1 + 255) / 256, 256>>>(x, perm, o_x5);

    dim3 g2(W / TX, H / TY, B);
    k2_canny<<<g2, 512>>>(o_mag);
    k3_dilate<<<g2, 512>>>(o_mag, o_d3, o_d5, o_d7, o_d9);
}